// round 7
// baseline (speedup 1.0000x reference)
#include <cuda_runtime.h>
#include <cuda_bf16.h>
#include <cstdint>
#include <cstddef>

// ---------------- problem constants ----------------
#define NBATCH 2
#define LSEQ   2048
#define DIM    1024
#define NH     16
#define DH     64
#define CHK    128
#define NCHK   (LSEQ / CHK)      // 16
#define MROWS  (NBATCH * LSEQ)   // 4096

// ---------------- device scratch (no allocs allowed) ----------------
__device__ __align__(16) float g_Q[MROWS * DIM];
__device__ __align__(16) float g_K[MROWS * DIM];
__device__ __align__(16) float g_V[MROWS * DIM];
__device__ __align__(16) float g_P[NBATCH * NH * NCHK * DH * DH];
__device__ __align__(16) __nv_bfloat16 g_Xhi[2][MROWS * DIM];   // 0=query 1=key
__device__ __align__(16) __nv_bfloat16 g_Xlo[2][MROWS * DIM];
__device__ __align__(16) __nv_bfloat16 g_Whi[3][DIM * DIM];     // Wq,Wk,Wv
__device__ __align__(16) __nv_bfloat16 g_Wlo[3][DIM * DIM];

// ---------------- small helpers ----------------
__device__ __forceinline__ uint32_t smem_u32(const void* p) {
    uint32_t a;
    asm("{ .reg .u64 t; cvta.to.shared.u64 t, %1; cvt.u32.u64 %0, t; }" : "=r"(a) : "l"(p));
    return a;
}
__device__ __forceinline__ void cp16(uint32_t s, const void* g) {
    asm volatile("cp.async.cg.shared.global [%0], [%1], 16;" :: "r"(s), "l"(g));
}
#define CP_COMMIT() asm volatile("cp.async.commit_group;" ::: "memory")
#define CP_WAIT1()  asm volatile("cp.async.wait_group 1;" ::: "memory")

__device__ __forceinline__ void mma16816(float* c, const uint32_t* a, const uint32_t* b) {
    asm volatile(
        "mma.sync.aligned.m16n8k16.row.col.f32.bf16.bf16.f32 "
        "{%0,%1,%2,%3}, {%4,%5,%6,%7}, {%8,%9}, {%0,%1,%2,%3};"
        : "+f"(c[0]), "+f"(c[1]), "+f"(c[2]), "+f"(c[3])
        : "r"(a[0]), "r"(a[1]), "r"(a[2]), "r"(a[3]), "r"(b[0]), "r"(b[1]));
}
__device__ __forceinline__ void ldsm4(uint32_t* r, uint32_t addr) {
    asm volatile("ldmatrix.sync.aligned.m8n8.x4.shared.b16 {%0,%1,%2,%3}, [%4];"
                 : "=r"(r[0]), "=r"(r[1]), "=r"(r[2]), "=r"(r[3]) : "r"(addr));
}

// ---------------- bf16 hi/lo split conversion ----------------
__global__ __launch_bounds__(256)
void conv_split(const float* __restrict__ q, const float* __restrict__ k,
                const float* __restrict__ wq, const float* __restrict__ wk,
                const float* __restrict__ wv)
{
    int y = blockIdx.y;
    const float* src;
    __nv_bfloat16 *hi, *lo;
    int n;
    switch (y) {
        case 0: src = q;  hi = g_Xhi[0]; lo = g_Xlo[0]; n = MROWS * DIM; break;
        case 1: src = k;  hi = g_Xhi[1]; lo = g_Xlo[1]; n = MROWS * DIM; break;
        case 2: src = wq; hi = g_Whi[0]; lo = g_Wlo[0]; n = DIM * DIM;   break;
        case 3: src = wk; hi = g_Whi[1]; lo = g_Wlo[1]; n = DIM * DIM;   break;
        default: src = wv; hi = g_Whi[2]; lo = g_Wlo[2]; n = DIM * DIM;  break;
    }
    int n4 = n >> 2;
    for (int i = blockIdx.x * blockDim.x + threadIdx.x; i < n4;
         i += gridDim.x * blockDim.x) {
        float4 f = ((const float4*)src)[i];
        __nv_bfloat16 h0 = __float2bfloat16(f.x);
        __nv_bfloat16 h1 = __float2bfloat16(f.y);
        __nv_bfloat16 h2 = __float2bfloat16(f.z);
        __nv_bfloat16 h3 = __float2bfloat16(f.w);
        __nv_bfloat16 l0 = __float2bfloat16(f.x - __bfloat162float(h0));
        __nv_bfloat16 l1 = __float2bfloat16(f.y - __bfloat162float(h1));
        __nv_bfloat16 l2 = __float2bfloat16(f.z - __bfloat162float(h2));
        __nv_bfloat16 l3 = __float2bfloat16(f.w - __bfloat162float(h3));
        ushort4 uh = make_ushort4(__bfloat16_as_ushort(h0), __bfloat16_as_ushort(h1),
                                  __bfloat16_as_ushort(h2), __bfloat16_as_ushort(h3));
        ushort4 ul = make_ushort4(__bfloat16_as_ushort(l0), __bfloat16_as_ushort(l1),
                                  __bfloat16_as_ushort(l2), __bfloat16_as_ushort(l3));
        ((ushort4*)hi)[i] = uh;
        ((ushort4*)lo)[i] = ul;
    }
}

// ---------------- HMMA projection GEMM (+ fused per-head softmax) ----------------
// Out[m,n] = sum_k X[m,k]*W[n,k], as Ahi*Bhi + Ahi*Blo + Alo*Bhi.
// 128x128 CTA tile, BK=64 halves (48 iters), 4 warps of 64x64 (128 threads),
// ldmatrix.x4, XOR-swizzled 128B rows, 3-stage cp.async ring.
// Epilogue (z<2): intra-warp softmax over each 64-col head segment.
#define STAGE_BYTES 32768
#define SMEM_TOTAL  (3 * STAGE_BYTES)     // 96 KB

__device__ __forceinline__ uint32_t swz(int row, int c) {
    return (uint32_t)(row * 128 + ((c ^ (row & 7)) << 4));
}

__global__ __launch_bounds__(128, 2)
void proj_hmma()
{
    extern __shared__ char smem[];
    const uint32_t sb = smem_u32(smem);

    const int tid = threadIdx.x;
    const int wid = tid >> 5;
    const int lane = tid & 31;
    const int wm = wid >> 1;       // 0..1 (row block)
    const int wn = wid & 1;        // 0..1 (col block = head segment)
    const int z = blockIdx.z;

    const __nv_bfloat16* __restrict__ Ahi = g_Xhi[z ? 1 : 0];
    const __nv_bfloat16* __restrict__ Alo = g_Xlo[z ? 1 : 0];
    const __nv_bfloat16* __restrict__ Bhi = g_Whi[z];
    const __nv_bfloat16* __restrict__ Blo = g_Wlo[z];
    float* __restrict__ Out = (z == 0) ? g_Q : (z == 1) ? g_K : g_V;

    const int m0 = blockIdx.y * 128;
    const int n0 = blockIdx.x * 128;

    float acc[4][8][4];
#pragma unroll
    for (int i = 0; i < 4; i++)
#pragma unroll
        for (int j = 0; j < 8; j++)
#pragma unroll
            for (int r = 0; r < 4; r++) acc[i][j][r] = 0.f;

    // loader: 128 threads, each owns one 128B row of A and B per stage
    auto load_tile = [&](int kk, int stg) {
        const int pass = kk >> 4;
        const int k0 = (kk & 15) * 64;
        const __nv_bfloat16* A = (pass < 2) ? Ahi : Alo;
        const __nv_bfloat16* B = (pass == 1) ? Blo : Bhi;
        const uint32_t sa = sb + stg * STAGE_BYTES;
        const uint32_t sbB = sa + 16384;
        const __nv_bfloat16* ga = A + (size_t)(m0 + tid) * DIM + k0;
        const __nv_bfloat16* gb = B + (size_t)(n0 + tid) * DIM + k0;
#pragma unroll
        for (int c = 0; c < 8; c++) {
            cp16(sa  + swz(tid, c), ga + c * 8);
            cp16(sbB + swz(tid, c), gb + c * 8);
        }
    };

    // fragment-load lane components
    const int a_row = (lane & 7) + ((lane >> 3) & 1) * 8;
    const int a_cofs = lane >> 4;
    const int b_row0 = ((lane >> 4) & 1) * 8 + (lane & 7);
    const int b_cofs = (lane >> 3) & 1;

    load_tile(0, 0); CP_COMMIT();
    load_tile(1, 1); CP_COMMIT();

    for (int kk = 0; kk < 48; kk++) {
        const int stg = kk % 3;
        CP_WAIT1();
        __syncthreads();
        if (kk + 2 < 48) { load_tile(kk + 2, (kk + 2) % 3); CP_COMMIT(); }

        const uint32_t sa = sb + stg * STAGE_BYTES;
        const uint32_t sbB = sa + 16384;

#pragma unroll
        for (int ks = 0; ks < 4; ks++) {
            const int c0 = ks * 2;
            uint32_t a[4][4], b[16];
#pragma unroll
            for (int i = 0; i < 4; i++) {
                const int r0 = wm * 64 + i * 16;
                ldsm4(a[i], sa + swz(r0 + a_row, c0 + a_cofs));
            }
#pragma unroll
            for (int jp = 0; jp < 4; jp++) {
                const int c0b = wn * 64 + jp * 16;
                ldsm4(&b[jp * 4], sbB + swz(c0b + b_row0, c0 + b_cofs));
            }
#pragma unroll
            for (int i = 0; i < 4; i++)
#pragma unroll
                for (int j = 0; j < 8; j++)
                    mma16816(acc[i][j], a[i], &b[j * 2]);
        }
    }

    // ---------------- epilogue ----------------
    const int g = lane >> 2;
    const int tg = lane & 3;

    if (z < 2) {
        // softmax over this warp's 64-col head segment; each row's 64 cols live
        // in 4 lanes (tg) x 8 j x 2 -> shfl over tg only (xor 1, 2).
#pragma unroll
        for (int i = 0; i < 4; i++)
#pragma unroll
            for (int h = 0; h < 2; h++) {
                float m = acc[i][0][h * 2];
#pragma unroll
                for (int j = 0; j < 8; j++) {
                    m = fmaxf(m, acc[i][j][h * 2]);
                    m = fmaxf(m, acc[i][j][h * 2 + 1]);
                }
                m = fmaxf(m, __shfl_xor_sync(0xffffffffu, m, 1));
                m = fmaxf(m, __shfl_xor_sync(0xffffffffu, m, 2));
                float s = 0.f;
#pragma unroll
                for (int j = 0; j < 8; j++) {
                    float e0 = __expf(acc[i][j][h * 2]     - m);
                    float e1 = __expf(acc[i][j][h * 2 + 1] - m);
                    acc[i][j][h * 2] = e0; acc[i][j][h * 2 + 1] = e1;
                    s += e0 + e1;
                }
                s += __shfl_xor_sync(0xffffffffu, s, 1);
                s += __shfl_xor_sync(0xffffffffu, s, 2);
                float inv = 1.0f / s;
#pragma unroll
                for (int j = 0; j < 8; j++) {
                    acc[i][j][h * 2]     *= inv;
                    acc[i][j][h * 2 + 1] *= inv;
                }
            }
    }

    // store fp32
#pragma unroll
    for (int i = 0; i < 4; i++) {
        const int r0 = m0 + wm * 64 + i * 16 + g;
#pragma unroll
        for (int j = 0; j < 8; j++) {
            const int cc = n0 + wn * 64 + j * 8 + tg * 2;
            *(float2*)&Out[(size_t)r0 * DIM + cc] = make_float2(acc[i][j][0], acc[i][j][1]);
            *(float2*)&Out[(size_t)(r0 + 8) * DIM + cc] = make_float2(acc[i][j][2], acc[i][j][3]);
        }
    }
}

// ---------------- per-chunk KV outer-product sums ----------------
__global__ __launch_bounds__(256)
void chunk_kv()
{
    extern __shared__ float sm[];
    float* ks = sm;          // 128*64
    float* vs = sm + 8192;   // 128*64

    const int c = blockIdx.x;
    const int nh = blockIdx.y;
    const int n = nh >> 4, h = nh & 15;
    const int t0 = c * CHK;
    const size_t base = ((size_t)(n * LSEQ + t0)) * DIM + h * DH;

    for (int idx = threadIdx.x; idx < CHK * DH; idx += 256) {
        int row = idx >> 6, col = idx & 63;
        ks[idx] = g_K[base + (size_t)row * DIM + col];
        vs[idx] = g_V[base + (size_t)row * DIM + col];
    }
    __syncthreads();

    const int tx = threadIdx.x & 15;
    const int ty = threadIdx.x >> 4;
    float acc[4][4];
#pragma unroll
    for (int i = 0; i < 4; i++)
#pragma unroll
        for (int j = 0; j < 4; j++) acc[i][j] = 0.f;

    for (int t = 0; t < CHK; t++) {
        float a[4], b[4];
#pragma unroll
        for (int i = 0; i < 4; i++) a[i] = ks[t * 64 + ty * 4 + i];
#pragma unroll
        for (int j = 0; j < 4; j++) b[j] = vs[t * 64 + tx * 4 + j];
#pragma unroll
        for (int i = 0; i < 4; i++)
#pragma unroll
            for (int j = 0; j < 4; j++)
                acc[i][j] = fmaf(a[i], b[j], acc[i][j]);
    }

    float* P = g_P + ((size_t)nh * NCHK + c) * (DH * DH);
#pragma unroll
    for (int i = 0; i < 4; i++)
#pragma unroll
        for (int j = 0; j < 4; j++)
            P[(ty * 4 + i) * 64 + tx * 4 + j] = acc[i][j];
}

// ---------------- exclusive prefix over chunks ----------------
__global__ __launch_bounds__(512)
void prefix_kv()
{
    const int nh = blockIdx.x >> 3;
    const int slab = blockIdx.x & 7;
    float* P = g_P + (size_t)nh * NCHK * (DH * DH);
    const int idx = slab * 512 + threadIdx.x;
    float run = 0.f;
#pragma unroll
    for (int c = 0; c < NCHK; c++) {
        float t = P[c * (DH * DH) + idx];
        P[c * (DH * DH) + idx] = run;
        run += t;
    }
}

// ---------------- attention output ----------------
__global__ __launch_bounds__(256)
void attn_out(float* __restrict__ out)
{
    extern __shared__ float sm[];
    float* qs = sm;            // 128*64
    float* Am = sm + 8192;     // 128*128
    float* R2 = sm + 24576;    // stage1: kT; stage2: vs + Ss

    const int c = blockIdx.x;
    const int nh = blockIdx.y;
    const int n = nh >> 4, h = nh & 15;
    const int t0 = c * CHK;
    const size_t base = ((size_t)(n * LSEQ + t0)) * DIM + h * DH;
    const int tid = threadIdx.x;
    const int tx = tid & 15;
    const int ty = tid >> 4;

    float* kT = R2;
    for (int idx = tid; idx < CHK * DH; idx += 256) {
        int row = idx >> 6, col = idx & 63;
        float qv = g_Q[base + (size_t)row * DIM + col];
        float kv = g_K[base + (size_t)row * DIM + col];
        qs[idx] = qv;
        kT[col * CHK + row] = kv;
    }
    __syncthreads();

    {
        float acc[8][8];
#pragma unroll
        for (int i = 0; i < 8; i++)
#pragma unroll
            for (int j = 0; j < 8; j++) acc[i][j] = 0.f;

        for (int d = 0; d < DH; d++) {
            float a[8], b[8];
#pragma unroll
            for (int i = 0; i < 8; i++) a[i] = qs[(ty * 8 + i) * 64 + d];
#pragma unroll
            for (int j = 0; j < 8; j++) b[j] = kT[d * CHK + tx * 8 + j];
#pragma unroll
            for (int i = 0; i < 8; i++)
#pragma unroll
                for (int j = 0; j < 8; j++)
                    acc[i][j] = fmaf(a[i], b[j], acc[i][j]);
        }
#pragma unroll
        for (int i = 0; i < 8; i++) {
            int r = ty * 8 + i;
#pragma unroll
            for (int j = 0; j < 8; j++) {
                int s = tx * 8 + j;
                Am[r * CHK + s] = (s <= r) ? acc[i][j] : 0.f;
            }
        }
    }
    __syncthreads();

    float* vs = R2;
    float* Ss = R2 + 8192;
    for (int idx = tid; idx < CHK * DH; idx += 256) {
        int row = idx >> 6, col = idx & 63;
        vs[idx] = g_V[base + (size_t)row * DIM + col];
    }
    {
        const float* Pp = g_P + ((size_t)nh * NCHK + c) * (DH * DH);
        for (int idx = tid; idx < DH * DH; idx += 256) Ss[idx] = Pp[idx];
    }
    __syncthreads();

    float o[8][4];
#pragma unroll
    for (int i = 0; i < 8; i++)
#pragma unroll
        for (int j = 0; j < 4; j++) o[i][j] = 0.f;

    for (int d = 0; d < DH; d++) {
        float a[8], b[4];
#pragma unroll
        for (int i = 0; i < 8; i++) a[i] = qs[(ty * 8 + i) * 64 + d];
#pragma unroll
        for (int j = 0; j < 4; j++) b[j] = Ss[d * 64 + tx * 4 + j];
#pragma unroll
        for (int i = 0; i < 8; i++)
#pragma unroll
            for (int j = 0; j < 4; j++)
                o[i][j] = fmaf(a[i], b[j], o[i][j]);
    }
    // causal: A[r][s] = 0 for s > r; warp rows reach 16*warp+15 -> bound s.
    const int sHi = ((tid >> 5) + 1) * 16;
    for (int s = 0; s < sHi; s++) {
        float a[8], b[4];
#pragma unroll
        for (int i = 0; i < 8; i++) a[i] = Am[(ty * 8 + i) * CHK + s];
#pragma unroll
        for (int j = 0; j < 4; j++) b[j] = vs[s * 64 + tx * 4 + j];
#pragma unroll
        for (int i = 0; i < 8; i++)
#pragma unroll
            for (int j = 0; j < 4; j++)
                o[i][j] = fmaf(a[i], b[j], o[i][j]);
    }

#pragma unroll
    for (int i = 0; i < 8; i++) {
        int r = ty * 8 + i;
#pragma unroll
        for (int j = 0; j < 4; j++)
            out[base + (size_t)r * DIM + tx * 4 + j] = o[i][j];
    }
}

// ---------------------------------------------------------------------------
extern "C" void kernel_launch(void* const* d_in, const int* in_sizes, int n_in,
                              void* d_out, int out_size)
{
    const float* query = (const float*)d_in[0];
    const float* key   = (const float*)d_in[1];
    const float* Wq    = (const float*)d_in[2];
    const float* Wk    = (const float*)d_in[3];
    const float* Wv    = (const float*)d_in[4];
    float* out = (float*)d_out;

    cudaFuncSetAttribute(proj_hmma, cudaFuncAttributeMaxDynamicSharedMemorySize, SMEM_TOTAL);
    cudaFuncSetAttribute(chunk_kv, cudaFuncAttributeMaxDynamicSharedMemorySize, 65536);
    cudaFuncSetAttribute(attn_out, cudaFuncAttributeMaxDynamicSharedMemorySize, 147456);

    // 1. split fp32 -> bf16 hi/lo
    conv_split<<<dim3(128, 5), 256>>>(query, key, Wq, Wk, Wv);

    // 2. projections on HMMA (z: 0=Q,1=K,2=V) with fused per-head softmax
    proj_hmma<<<dim3(8, 32, 3), 128, SMEM_TOTAL>>>();

    // 3. chunked causal linear attention
    dim3 agrid(NCHK, NBATCH * NH);
    chunk_kv<<<agrid, 256, 65536>>>();
    prefix_kv<<<NBATCH * NH * 8, 512>>>();
    attn_out<<<agrid, 256, 147456>>>(out);
}

// round 8
// speedup vs baseline: 1.2686x; 1.2686x over previous
#include <cuda_runtime.h>
#include <cuda_bf16.h>
#include <cstdint>
#include <cstddef>

// ---------------- problem constants ----------------
#define NBATCH 2
#define LSEQ   2048
#define DIM    1024
#define NH     16
#define DH     64
#define CHK    128
#define NCHK   (LSEQ / CHK)      // 16
#define MROWS  (NBATCH * LSEQ)   // 4096

// ---------------- device scratch (no allocs allowed) ----------------
__device__ __align__(16) float g_Q[MROWS * DIM];
__device__ __align__(16) float g_K[MROWS * DIM];
__device__ __align__(16) float g_V[MROWS * DIM];
__device__ __align__(16) float g_P[NBATCH * NH * NCHK * DH * DH];
__device__ __align__(16) __nv_bfloat16 g_Xhi[2][MROWS * DIM];   // 0=query 1=key
__device__ __align__(16) __nv_bfloat16 g_Xlo[2][MROWS * DIM];
__device__ __align__(16) __nv_bfloat16 g_Whi[3][DIM * DIM];     // Wq,Wk,Wv
__device__ __align__(16) __nv_bfloat16 g_Wlo[3][DIM * DIM];

// ---------------- small helpers ----------------
__device__ __forceinline__ uint32_t smem_u32(const void* p) {
    uint32_t a;
    asm("{ .reg .u64 t; cvta.to.shared.u64 t, %1; cvt.u32.u64 %0, t; }" : "=r"(a) : "l"(p));
    return a;
}
__device__ __forceinline__ void cp16(uint32_t s, const void* g) {
    asm volatile("cp.async.cg.shared.global [%0], [%1], 16;" :: "r"(s), "l"(g));
}
#define CP_COMMIT() asm volatile("cp.async.commit_group;" ::: "memory")
#define CP_WAIT1()  asm volatile("cp.async.wait_group 1;" ::: "memory")

__device__ __forceinline__ void mma16816(float* c, const uint32_t* a, const uint32_t* b) {
    asm volatile(
        "mma.sync.aligned.m16n8k16.row.col.f32.bf16.bf16.f32 "
        "{%0,%1,%2,%3}, {%4,%5,%6,%7}, {%8,%9}, {%0,%1,%2,%3};"
        : "+f"(c[0]), "+f"(c[1]), "+f"(c[2]), "+f"(c[3])
        : "r"(a[0]), "r"(a[1]), "r"(a[2]), "r"(a[3]), "r"(b[0]), "r"(b[1]));
}
__device__ __forceinline__ void ldsm4(uint32_t* r, uint32_t addr) {
    asm volatile("ldmatrix.sync.aligned.m8n8.x4.shared.b16 {%0,%1,%2,%3}, [%4];"
                 : "=r"(r[0]), "=r"(r[1]), "=r"(r[2]), "=r"(r[3]) : "r"(addr));
}

// ---------------- bf16 hi/lo split conversion ----------------
__global__ __launch_bounds__(256)
void conv_split(const float* __restrict__ q, const float* __restrict__ k,
                const float* __restrict__ wq, const float* __restrict__ wk,
                const float* __restrict__ wv)
{
    int y = blockIdx.y;
    const float* src;
    __nv_bfloat16 *hi, *lo;
    int n;
    switch (y) {
        case 0: src = q;  hi = g_Xhi[0]; lo = g_Xlo[0]; n = MROWS * DIM; break;
        case 1: src = k;  hi = g_Xhi[1]; lo = g_Xlo[1]; n = MROWS * DIM; break;
        case 2: src = wq; hi = g_Whi[0]; lo = g_Wlo[0]; n = DIM * DIM;   break;
        case 3: src = wk; hi = g_Whi[1]; lo = g_Wlo[1]; n = DIM * DIM;   break;
        default: src = wv; hi = g_Whi[2]; lo = g_Wlo[2]; n = DIM * DIM;  break;
    }
    int n4 = n >> 2;
    for (int i = blockIdx.x * blockDim.x + threadIdx.x; i < n4;
         i += gridDim.x * blockDim.x) {
        float4 f = ((const float4*)src)[i];
        __nv_bfloat16 h0 = __float2bfloat16(f.x);
        __nv_bfloat16 h1 = __float2bfloat16(f.y);
        __nv_bfloat16 h2 = __float2bfloat16(f.z);
        __nv_bfloat16 h3 = __float2bfloat16(f.w);
        __nv_bfloat16 l0 = __float2bfloat16(f.x - __bfloat162float(h0));
        __nv_bfloat16 l1 = __float2bfloat16(f.y - __bfloat162float(h1));
        __nv_bfloat16 l2 = __float2bfloat16(f.z - __bfloat162float(h2));
        __nv_bfloat16 l3 = __float2bfloat16(f.w - __bfloat162float(h3));
        ushort4 uh = make_ushort4(__bfloat16_as_ushort(h0), __bfloat16_as_ushort(h1),
                                  __bfloat16_as_ushort(h2), __bfloat16_as_ushort(h3));
        ushort4 ul = make_ushort4(__bfloat16_as_ushort(l0), __bfloat16_as_ushort(l1),
                                  __bfloat16_as_ushort(l2), __bfloat16_as_ushort(l3));
        ((ushort4*)hi)[i] = uh;
        ((ushort4*)lo)[i] = ul;
    }
}

// ---------------- HMMA projection GEMM (+ fused per-head softmax) ----------------
// R6 configuration (measured best): 128x128 CTA tile, BK=64 halves (48 iters),
// 8 warps of 64x32 (256 threads), ldmatrix.x4, XOR-swizzled 128B rows,
// 3-stage cp.async ring. Epilogue (z<2): per-head softmax via smem reduction.
#define STAGE_BYTES 32768
#define SMEM_TOTAL  (3 * STAGE_BYTES)     // 96 KB

__device__ __forceinline__ uint32_t swz(int row, int c) {
    return (uint32_t)(row * 128 + ((c ^ (row & 7)) << 4));
}

__global__ __launch_bounds__(256, 2)
void proj_hmma()
{
    extern __shared__ char smem[];
    const uint32_t sb = smem_u32(smem);

    const int tid = threadIdx.x;
    const int wid = tid >> 5;
    const int lane = tid & 31;
    const int wm = wid >> 2;       // 0..1
    const int wn = wid & 3;        // 0..3
    const int z = blockIdx.z;

    const __nv_bfloat16* __restrict__ Ahi = g_Xhi[z ? 1 : 0];
    const __nv_bfloat16* __restrict__ Alo = g_Xlo[z ? 1 : 0];
    const __nv_bfloat16* __restrict__ Bhi = g_Whi[z];
    const __nv_bfloat16* __restrict__ Blo = g_Wlo[z];
    float* __restrict__ Out = (z == 0) ? g_Q : (z == 1) ? g_K : g_V;

    const int m0 = blockIdx.y * 128;
    const int n0 = blockIdx.x * 128;

    float acc[4][4][4];
#pragma unroll
    for (int i = 0; i < 4; i++)
#pragma unroll
        for (int j = 0; j < 4; j++)
#pragma unroll
            for (int r = 0; r < 4; r++) acc[i][j][r] = 0.f;

    const int lrow = tid >> 1;
    const int lc4  = (tid & 1) * 4;
    auto load_tile = [&](int kk, int stg) {
        const int pass = kk >> 4;
        const int k0 = (kk & 15) * 64;
        const __nv_bfloat16* A = (pass < 2) ? Ahi : Alo;
        const __nv_bfloat16* B = (pass == 1) ? Blo : Bhi;
        const uint32_t sa = sb + stg * STAGE_BYTES;
        const uint32_t sbB = sa + 16384;
        const __nv_bfloat16* ga = A + (size_t)(m0 + lrow) * DIM + k0 + lc4 * 8;
        const __nv_bfloat16* gb = B + (size_t)(n0 + lrow) * DIM + k0 + lc4 * 8;
#pragma unroll
        for (int c = 0; c < 4; c++) {
            cp16(sa  + swz(lrow, lc4 + c), ga + c * 8);
            cp16(sbB + swz(lrow, lc4 + c), gb + c * 8);
        }
    };

    const int a_row = (lane & 7) + ((lane >> 3) & 1) * 8;
    const int a_cofs = lane >> 4;
    const int b_row0 = ((lane >> 4) & 1) * 8 + (lane & 7);
    const int b_cofs = (lane >> 3) & 1;

    load_tile(0, 0); CP_COMMIT();
    load_tile(1, 1); CP_COMMIT();

    for (int kk = 0; kk < 48; kk++) {
        const int stg = kk % 3;
        CP_WAIT1();
        __syncthreads();
        if (kk + 2 < 48) { load_tile(kk + 2, (kk + 2) % 3); CP_COMMIT(); }

        const uint32_t sa = sb + stg * STAGE_BYTES;
        const uint32_t sbB = sa + 16384;

#pragma unroll
        for (int ks = 0; ks < 4; ks++) {
            const int c0 = ks * 2;
            uint32_t a[4][4], b[8];
#pragma unroll
            for (int i = 0; i < 4; i++) {
                const int r0 = wm * 64 + i * 16;
                ldsm4(a[i], sa + swz(r0 + a_row, c0 + a_cofs));
            }
#pragma unroll
            for (int jp = 0; jp < 2; jp++) {
                const int c0b = wn * 32 + jp * 16;
                ldsm4(&b[jp * 4], sbB + swz(c0b + b_row0, c0 + b_cofs));
            }
#pragma unroll
            for (int i = 0; i < 4; i++)
#pragma unroll
                for (int j = 0; j < 4; j++)
                    mma16816(acc[i][j], a[i], &b[j * 2]);
        }
    }

    // ---------------- epilogue ----------------
    const int g = lane >> 2;
    const int tg = lane & 3;
    __syncthreads();

    if (z < 2) {
        float* red = (float*)smem;   // [128 rows][2 seg][2 pair]
        const int seg = wn >> 1;
        const int pr = wn & 1;

        float ml[4][2];
#pragma unroll
        for (int i = 0; i < 4; i++)
#pragma unroll
            for (int h = 0; h < 2; h++) {
                float m = acc[i][0][h * 2];
#pragma unroll
                for (int j = 0; j < 4; j++) {
                    m = fmaxf(m, acc[i][j][h * 2]);
                    m = fmaxf(m, acc[i][j][h * 2 + 1]);
                }
                m = fmaxf(m, __shfl_xor_sync(0xffffffffu, m, 1));
                m = fmaxf(m, __shfl_xor_sync(0xffffffffu, m, 2));
                ml[i][h] = m;
            }
        if (tg == 0) {
#pragma unroll
            for (int i = 0; i < 4; i++)
#pragma unroll
                for (int h = 0; h < 2; h++) {
                    int row = wm * 64 + i * 16 + h * 8 + g;
                    red[(row * 2 + seg) * 2 + pr] = ml[i][h];
                }
        }
        __syncthreads();
        float mseg[4][2];
#pragma unroll
        for (int i = 0; i < 4; i++)
#pragma unroll
            for (int h = 0; h < 2; h++) {
                int row = wm * 64 + i * 16 + h * 8 + g;
                mseg[i][h] = fmaxf(red[(row * 2 + seg) * 2 + 0],
                                   red[(row * 2 + seg) * 2 + 1]);
            }
        __syncthreads();

        float sl[4][2];
#pragma unroll
        for (int i = 0; i < 4; i++)
#pragma unroll
            for (int h = 0; h < 2; h++) {
                float s = 0.f;
#pragma unroll
                for (int j = 0; j < 4; j++) {
                    float e0 = __expf(acc[i][j][h * 2]     - mseg[i][h]);
                    float e1 = __expf(acc[i][j][h * 2 + 1] - mseg[i][h]);
                    acc[i][j][h * 2] = e0; acc[i][j][h * 2 + 1] = e1;
                    s += e0 + e1;
                }
                s += __shfl_xor_sync(0xffffffffu, s, 1);
                s += __shfl_xor_sync(0xffffffffu, s, 2);
                sl[i][h] = s;
            }
        if (tg == 0) {
#pragma unroll
            for (int i = 0; i < 4; i++)
#pragma unroll
                for (int h = 0; h < 2; h++) {
                    int row = wm * 64 + i * 16 + h * 8 + g;
                    red[(row * 2 + seg) * 2 + pr] = sl[i][h];
                }
        }
        __syncthreads();
#pragma unroll
        for (int i = 0; i < 4; i++)
#pragma unroll
            for (int h = 0; h < 2; h++) {
                int row = wm * 64 + i * 16 + h * 8 + g;
                float inv = 1.0f / (red[(row * 2 + seg) * 2 + 0] +
                                    red[(row * 2 + seg) * 2 + 1]);
#pragma unroll
                for (int j = 0; j < 4; j++) {
                    acc[i][j][h * 2]     *= inv;
                    acc[i][j][h * 2 + 1] *= inv;
                }
            }
    }

#pragma unroll
    for (int i = 0; i < 4; i++) {
        const int r0 = m0 + wm * 64 + i * 16 + g;
#pragma unroll
        for (int j = 0; j < 4; j++) {
            const int cc = n0 + wn * 32 + j * 8 + tg * 2;
            *(float2*)&Out[(size_t)r0 * DIM + cc] = make_float2(acc[i][j][0], acc[i][j][1]);
            *(float2*)&Out[(size_t)(r0 + 8) * DIM + cc] = make_float2(acc[i][j][2], acc[i][j][3]);
        }
    }
}

// ---------------- per-chunk KV outer-product sums ----------------
__global__ __launch_bounds__(256)
void chunk_kv()
{
    extern __shared__ float sm[];
    float* ks = sm;          // 128*64
    float* vs = sm + 8192;   // 128*64

    const int c = blockIdx.x;
    const int nh = blockIdx.y;
    const int n = nh >> 4, h = nh & 15;
    const int t0 = c * CHK;
    const size_t base = ((size_t)(n * LSEQ + t0)) * DIM + h * DH;

    for (int idx = threadIdx.x; idx < CHK * DH; idx += 256) {
        int row = idx >> 6, col = idx & 63;
        ks[idx] = g_K[base + (size_t)row * DIM + col];
        vs[idx] = g_V[base + (size_t)row * DIM + col];
    }
    __syncthreads();

    const int tx = threadIdx.x & 15;
    const int ty = threadIdx.x >> 4;
    float acc[4][4];
#pragma unroll
    for (int i = 0; i < 4; i++)
#pragma unroll
        for (int j = 0; j < 4; j++) acc[i][j] = 0.f;

    for (int t = 0; t < CHK; t++) {
        float a[4], b[4];
#pragma unroll
        for (int i = 0; i < 4; i++) a[i] = ks[t * 64 + ty * 4 + i];
#pragma unroll
        for (int j = 0; j < 4; j++) b[j] = vs[t * 64 + tx * 4 + j];
#pragma unroll
        for (int i = 0; i < 4; i++)
#pragma unroll
            for (int j = 0; j < 4; j++)
                acc[i][j] = fmaf(a[i], b[j], acc[i][j]);
    }

    float* P = g_P + ((size_t)nh * NCHK + c) * (DH * DH);
#pragma unroll
    for (int i = 0; i < 4; i++)
#pragma unroll
        for (int j = 0; j < 4; j++)
            P[(ty * 4 + i) * 64 + tx * 4 + j] = acc[i][j];
}

// ---------------- exclusive prefix over chunks ----------------
__global__ __launch_bounds__(512)
void prefix_kv()
{
    const int nh = blockIdx.x >> 3;
    const int slab = blockIdx.x & 7;
    float* P = g_P + (size_t)nh * NCHK * (DH * DH);
    const int idx = slab * 512 + threadIdx.x;
    float run = 0.f;
#pragma unroll
    for (int c = 0; c < NCHK; c++) {
        float t = P[c * (DH * DH) + idx];
        P[c * (DH * DH) + idx] = run;
        run += t;
    }
}

// ---------------- attention output ----------------
// qs padded to stride 65 (bank-conflict-free across 8-row strides).
// Stage 1 uses a 4x2 grid of 32x64 warp blocks: warps wholly above the
// causal diagonal (wid 1,3) skip the entire FMA loop (bit-exact zeros).
#define QSP 65
#define AO_QS    0
#define AO_AM    (128 * QSP)               // 8320
#define AO_R2    (AO_AM + 128 * 128)       // 24704
#define AO_FLTS  (AO_R2 + 12288)           // 36992 floats
#define AO_BYTES (AO_FLTS * 4)             // 147968

__global__ __launch_bounds__(256)
void attn_out(float* __restrict__ out)
{
    extern __shared__ float sm[];
    float* qs = sm + AO_QS;    // 128 x 65
    float* Am = sm + AO_AM;    // 128 x 128
    float* R2 = sm + AO_R2;    // stage1: kT (64x128); stage2: vs(8192)+Ss(4096)

    const int c = blockIdx.x;
    const int nh = blockIdx.y;
    const int n = nh >> 4, h = nh & 15;
    const int t0 = c * CHK;
    const size_t base = ((size_t)(n * LSEQ + t0)) * DIM + h * DH;
    const int tid = threadIdx.x;
    const int lane = tid & 31;
    const int wid = tid >> 5;
    const int tx = tid & 15;
    const int ty = tid >> 4;

    float* kT = R2;
    for (int idx = tid; idx < CHK * DH; idx += 256) {
        int row = idx >> 6, col = idx & 63;
        float qv = g_Q[base + (size_t)row * DIM + col];
        float kv = g_K[base + (size_t)row * DIM + col];
        qs[row * QSP + col] = qv;
        kT[col * CHK + row] = kv;
    }
    __syncthreads();

    // Stage 1: A = causal(q @ k^T). Warp blocks 32x64: rblk=wid>>1, cblk=wid&1.
    {
        const int rblk = wid >> 1;           // 0..3
        const int cblk = wid & 1;            // 0..1
        const int rr0 = rblk * 32 + (lane >> 3) * 8;   // thread row base
        const int ss0 = cblk * 64 + (lane & 7) * 8;    // thread col base
        const bool skip = (cblk == 1) && (rblk <= 1);  // wholly above diagonal

        if (skip) {
#pragma unroll
            for (int i = 0; i < 8; i++)
#pragma unroll
                for (int j = 0; j < 8; j++)
                    Am[(rr0 + i) * CHK + ss0 + j] = 0.f;
        } else {
            float acc[8][8];
#pragma unroll
            for (int i = 0; i < 8; i++)
#pragma unroll
                for (int j = 0; j < 8; j++) acc[i][j] = 0.f;

            for (int d = 0; d < DH; d++) {
                float a[8], b[8];
#pragma unroll
                for (int i = 0; i < 8; i++) a[i] = qs[(rr0 + i) * QSP + d];
#pragma unroll
                for (int j = 0; j < 8; j++) b[j] = kT[d * CHK + ss0 + j];
#pragma unroll
                for (int i = 0; i < 8; i++)
#pragma unroll
                    for (int j = 0; j < 8; j++)
                        acc[i][j] = fmaf(a[i], b[j], acc[i][j]);
            }
#pragma unroll
            for (int i = 0; i < 8; i++) {
                int r = rr0 + i;
#pragma unroll
                for (int j = 0; j < 8; j++) {
                    int s = ss0 + j;
                    Am[r * CHK + s] = (s <= r) ? acc[i][j] : 0.f;
                }
            }
        }
    }
    __syncthreads();

    float* vs = R2;
    float* Ss = R2 + 8192;
    for (int idx = tid; idx < CHK * DH; idx += 256) {
        int row = idx >> 6, col = idx & 63;
        vs[idx] = g_V[base + (size_t)row * DIM + col];
    }
    {
        const float* Pp = g_P + ((size_t)nh * NCHK + c) * (DH * DH);
        for (int idx = tid; idx < DH * DH; idx += 256) Ss[idx] = Pp[idx];
    }
    __syncthreads();

    float o[8][4];
#pragma unroll
    for (int i = 0; i < 8; i++)
#pragma unroll
        for (int j = 0; j < 4; j++) o[i][j] = 0.f;

    for (int d = 0; d < DH; d++) {
        float a[8], b[4];
#pragma unroll
        for (int i = 0; i < 8; i++) a[i] = qs[(ty * 8 + i) * QSP + d];
#pragma unroll
        for (int j = 0; j < 4; j++) b[j] = Ss[d * 64 + tx * 4 + j];
#pragma unroll
        for (int i = 0; i < 8; i++)
#pragma unroll
            for (int j = 0; j < 4; j++)
                o[i][j] = fmaf(a[i], b[j], o[i][j]);
    }
    // causal: A[r][s] = 0 for s > r; warp rows reach 16*warp+15 -> bound s.
    const int sHi = (wid + 1) * 16;
    for (int s = 0; s < sHi; s++) {
        float a[8], b[4];
#pragma unroll
        for (int i = 0; i < 8; i++) a[i] = Am[(ty * 8 + i) * CHK + s];
#pragma unroll
        for (int j = 0; j < 4; j++) b[j] = vs[s * 64 + tx * 4 + j];
#pragma unroll
        for (int i = 0; i < 8; i++)
#pragma unroll
            for (int j = 0; j < 4; j++)
                o[i][j] = fmaf(a[i], b[j], o[i][j]);
    }

#pragma unroll
    for (int i = 0; i < 8; i++) {
        int r = ty * 8 + i;
#pragma unroll
        for (int j = 0; j < 4; j++)
            out[base + (size_t)r * DIM + tx * 4 + j] = o[i][j];
    }
}

// ---------------------------------------------------------------------------
extern "C" void kernel_launch(void* const* d_in, const int* in_sizes, int n_in,
                              void* d_out, int out_size)
{
    const float* query = (const float*)d_in[0];
    const float* key   = (const float*)d_in[1];
    const float* Wq    = (const float*)d_in[2];
    const float* Wk    = (const float*)d_in[3];
    const float* Wv    = (const float*)d_in[4];
    float* out = (float*)d_out;

    cudaFuncSetAttribute(proj_hmma, cudaFuncAttributeMaxDynamicSharedMemorySize, SMEM_TOTAL);
    cudaFuncSetAttribute(chunk_kv, cudaFuncAttributeMaxDynamicSharedMemorySize, 65536);
    cudaFuncSetAttribute(attn_out, cudaFuncAttributeMaxDynamicSharedMemorySize, AO_BYTES);

    // 1. split fp32 -> bf16 hi/lo
    conv_split<<<dim3(128, 5), 256>>>(query, key, Wq, Wk, Wv);

    // 2. projections on HMMA (z: 0=Q,1=K,2=V) with fused per-head softmax
    proj_hmma<<<dim3(8, 32, 3), 256, SMEM_TOTAL>>>();

    // 3. chunked causal linear attention
    dim3 agrid(NCHK, NBATCH * NH);
    chunk_kv<<<agrid, 256, 65536>>>();
    prefix_kv<<<NBATCH * NH * 8, 512>>>();
    attn_out<<<agrid, 256, AO_BYTES>>>(out);
}

// round 9
// speedup vs baseline: 1.3068x; 1.0301x over previous
#include <cuda_runtime.h>
#include <cuda_bf16.h>
#include <cstdint>
#include <cstddef>

// ---------------- problem constants ----------------
#define NBATCH 2
#define LSEQ   2048
#define DIM    1024
#define NH     16
#define DH     64
#define CHK    128
#define NCHK   (LSEQ / CHK)      // 16
#define MROWS  (NBATCH * LSEQ)   // 4096

// ---------------- device scratch (no allocs allowed) ----------------
__device__ __align__(16) float g_Q[MROWS * DIM];
__device__ __align__(16) float g_K[MROWS * DIM];
__device__ __align__(16) float g_V[MROWS * DIM];
__device__ __align__(16) float g_P[NBATCH * NH * NCHK * DH * DH];
__device__ __align__(16) __nv_bfloat16 g_Xhi[2][MROWS * DIM];   // 0=query 1=key
__device__ __align__(16) __nv_bfloat16 g_Xlo[2][MROWS * DIM];
__device__ __align__(16) __nv_bfloat16 g_Whi[3][DIM * DIM];     // Wq,Wk,Wv
__device__ __align__(16) __nv_bfloat16 g_Wlo[3][DIM * DIM];

// ---------------- small helpers ----------------
__device__ __forceinline__ uint32_t smem_u32(const void* p) {
    uint32_t a;
    asm("{ .reg .u64 t; cvta.to.shared.u64 t, %1; cvt.u32.u64 %0, t; }" : "=r"(a) : "l"(p));
    return a;
}
__device__ __forceinline__ void cp16(uint32_t s, const void* g) {
    asm volatile("cp.async.cg.shared.global [%0], [%1], 16;" :: "r"(s), "l"(g));
}
#define CP_COMMIT() asm volatile("cp.async.commit_group;" ::: "memory")
#define CP_WAIT1()  asm volatile("cp.async.wait_group 1;" ::: "memory")

__device__ __forceinline__ void mma16816(float* c, const uint32_t* a, const uint32_t* b) {
    asm volatile(
        "mma.sync.aligned.m16n8k16.row.col.f32.bf16.bf16.f32 "
        "{%0,%1,%2,%3}, {%4,%5,%6,%7}, {%8,%9}, {%0,%1,%2,%3};"
        : "+f"(c[0]), "+f"(c[1]), "+f"(c[2]), "+f"(c[3])
        : "r"(a[0]), "r"(a[1]), "r"(a[2]), "r"(a[3]), "r"(b[0]), "r"(b[1]));
}
__device__ __forceinline__ void ldsm4(uint32_t* r, uint32_t addr) {
    asm volatile("ldmatrix.sync.aligned.m8n8.x4.shared.b16 {%0,%1,%2,%3}, [%4];"
                 : "=r"(r[0]), "=r"(r[1]), "=r"(r[2]), "=r"(r[3]) : "r"(addr));
}

// ---------------- bf16 hi/lo split conversion ----------------
__global__ __launch_bounds__(256)
void conv_split(const float* __restrict__ q, const float* __restrict__ k,
                const float* __restrict__ wq, const float* __restrict__ wk,
                const float* __restrict__ wv)
{
    int y = blockIdx.y;
    const float* src;
    __nv_bfloat16 *hi, *lo;
    int n;
    switch (y) {
        case 0: src = q;  hi = g_Xhi[0]; lo = g_Xlo[0]; n = MROWS * DIM; break;
        case 1: src = k;  hi = g_Xhi[1]; lo = g_Xlo[1]; n = MROWS * DIM; break;
        case 2: src = wq; hi = g_Whi[0]; lo = g_Wlo[0]; n = DIM * DIM;   break;
        case 3: src = wk; hi = g_Whi[1]; lo = g_Wlo[1]; n = DIM * DIM;   break;
        default: src = wv; hi = g_Whi[2]; lo = g_Wlo[2]; n = DIM * DIM;  break;
    }
    int n4 = n >> 2;
    for (int i = blockIdx.x * blockDim.x + threadIdx.x; i < n4;
         i += gridDim.x * blockDim.x) {
        float4 f = ((const float4*)src)[i];
        __nv_bfloat16 h0 = __float2bfloat16(f.x);
        __nv_bfloat16 h1 = __float2bfloat16(f.y);
        __nv_bfloat16 h2 = __float2bfloat16(f.z);
        __nv_bfloat16 h3 = __float2bfloat16(f.w);
        __nv_bfloat16 l0 = __float2bfloat16(f.x - __bfloat162float(h0));
        __nv_bfloat16 l1 = __float2bfloat16(f.y - __bfloat162float(h1));
        __nv_bfloat16 l2 = __float2bfloat16(f.z - __bfloat162float(h2));
        __nv_bfloat16 l3 = __float2bfloat16(f.w - __bfloat162float(h3));
        ushort4 uh = make_ushort4(__bfloat16_as_ushort(h0), __bfloat16_as_ushort(h1),
                                  __bfloat16_as_ushort(h2), __bfloat16_as_ushort(h3));
        ushort4 ul = make_ushort4(__bfloat16_as_ushort(l0), __bfloat16_as_ushort(l1),
                                  __bfloat16_as_ushort(l2), __bfloat16_as_ushort(l3));
        ((ushort4*)hi)[i] = uh;
        ((ushort4*)lo)[i] = ul;
    }
}

// ---------------- HMMA projection GEMM (+ fused per-head softmax) ----------------
// Measured-best config: 128x128 CTA tile, BK=64 halves (48 iters),
// 8 warps of 64x32 (256 threads), ldmatrix.x4, XOR-swizzled 128B rows,
// 3-stage cp.async ring. Epilogue (z<2): per-head softmax via smem reduction.
#define STAGE_BYTES 32768
#define SMEM_TOTAL  (3 * STAGE_BYTES)     // 96 KB

__device__ __forceinline__ uint32_t swz(int row, int c) {
    return (uint32_t)(row * 128 + ((c ^ (row & 7)) << 4));
}

__global__ __launch_bounds__(256, 2)
void proj_hmma()
{
    extern __shared__ char smem[];
    const uint32_t sb = smem_u32(smem);

    const int tid = threadIdx.x;
    const int wid = tid >> 5;
    const int lane = tid & 31;
    const int wm = wid >> 2;       // 0..1
    const int wn = wid & 3;        // 0..3
    const int z = blockIdx.z;

    const __nv_bfloat16* __restrict__ Ahi = g_Xhi[z ? 1 : 0];
    const __nv_bfloat16* __restrict__ Alo = g_Xlo[z ? 1 : 0];
    const __nv_bfloat16* __restrict__ Bhi = g_Whi[z];
    const __nv_bfloat16* __restrict__ Blo = g_Wlo[z];
    float* __restrict__ Out = (z == 0) ? g_Q : (z == 1) ? g_K : g_V;

    const int m0 = blockIdx.y * 128;
    const int n0 = blockIdx.x * 128;

    float acc[4][4][4];
#pragma unroll
    for (int i = 0; i < 4; i++)
#pragma unroll
        for (int j = 0; j < 4; j++)
#pragma unroll
            for (int r = 0; r < 4; r++) acc[i][j][r] = 0.f;

    const int lrow = tid >> 1;
    const int lc4  = (tid & 1) * 4;
    auto load_tile = [&](int kk, int stg) {
        const int pass = kk >> 4;
        const int k0 = (kk & 15) * 64;
        const __nv_bfloat16* A = (pass < 2) ? Ahi : Alo;
        const __nv_bfloat16* B = (pass == 1) ? Blo : Bhi;
        const uint32_t sa = sb + stg * STAGE_BYTES;
        const uint32_t sbB = sa + 16384;
        const __nv_bfloat16* ga = A + (size_t)(m0 + lrow) * DIM + k0 + lc4 * 8;
        const __nv_bfloat16* gb = B + (size_t)(n0 + lrow) * DIM + k0 + lc4 * 8;
#pragma unroll
        for (int c = 0; c < 4; c++) {
            cp16(sa  + swz(lrow, lc4 + c), ga + c * 8);
            cp16(sbB + swz(lrow, lc4 + c), gb + c * 8);
        }
    };

    const int a_row = (lane & 7) + ((lane >> 3) & 1) * 8;
    const int a_cofs = lane >> 4;
    const int b_row0 = ((lane >> 4) & 1) * 8 + (lane & 7);
    const int b_cofs = (lane >> 3) & 1;

    load_tile(0, 0); CP_COMMIT();
    load_tile(1, 1); CP_COMMIT();

    for (int kk = 0; kk < 48; kk++) {
        const int stg = kk % 3;
        CP_WAIT1();
        __syncthreads();
        if (kk + 2 < 48) { load_tile(kk + 2, (kk + 2) % 3); CP_COMMIT(); }

        const uint32_t sa = sb + stg * STAGE_BYTES;
        const uint32_t sbB = sa + 16384;

#pragma unroll
        for (int ks = 0; ks < 4; ks++) {
            const int c0 = ks * 2;
            uint32_t a[4][4], b[8];
#pragma unroll
            for (int i = 0; i < 4; i++) {
                const int r0 = wm * 64 + i * 16;
                ldsm4(a[i], sa + swz(r0 + a_row, c0 + a_cofs));
            }
#pragma unroll
            for (int jp = 0; jp < 2; jp++) {
                const int c0b = wn * 32 + jp * 16;
                ldsm4(&b[jp * 4], sbB + swz(c0b + b_row0, c0 + b_cofs));
            }
#pragma unroll
            for (int i = 0; i < 4; i++)
#pragma unroll
                for (int j = 0; j < 4; j++)
                    mma16816(acc[i][j], a[i], &b[j * 2]);
        }
    }

    // ---------------- epilogue ----------------
    const int g = lane >> 2;
    const int tg = lane & 3;
    __syncthreads();

    if (z < 2) {
        float* red = (float*)smem;   // [128 rows][2 seg][2 pair]
        const int seg = wn >> 1;
        const int pr = wn & 1;

        float ml[4][2];
#pragma unroll
        for (int i = 0; i < 4; i++)
#pragma unroll
            for (int h = 0; h < 2; h++) {
                float m = acc[i][0][h * 2];
#pragma unroll
                for (int j = 0; j < 4; j++) {
                    m = fmaxf(m, acc[i][j][h * 2]);
                    m = fmaxf(m, acc[i][j][h * 2 + 1]);
                }
                m = fmaxf(m, __shfl_xor_sync(0xffffffffu, m, 1));
                m = fmaxf(m, __shfl_xor_sync(0xffffffffu, m, 2));
                ml[i][h] = m;
            }
        if (tg == 0) {
#pragma unroll
            for (int i = 0; i < 4; i++)
#pragma unroll
                for (int h = 0; h < 2; h++) {
                    int row = wm * 64 + i * 16 + h * 8 + g;
                    red[(row * 2 + seg) * 2 + pr] = ml[i][h];
                }
        }
        __syncthreads();
        float mseg[4][2];
#pragma unroll
        for (int i = 0; i < 4; i++)
#pragma unroll
            for (int h = 0; h < 2; h++) {
                int row = wm * 64 + i * 16 + h * 8 + g;
                mseg[i][h] = fmaxf(red[(row * 2 + seg) * 2 + 0],
                                   red[(row * 2 + seg) * 2 + 1]);
            }
        __syncthreads();

        float sl[4][2];
#pragma unroll
        for (int i = 0; i < 4; i++)
#pragma unroll
            for (int h = 0; h < 2; h++) {
                float s = 0.f;
#pragma unroll
                for (int j = 0; j < 4; j++) {
                    float e0 = __expf(acc[i][j][h * 2]     - mseg[i][h]);
                    float e1 = __expf(acc[i][j][h * 2 + 1] - mseg[i][h]);
                    acc[i][j][h * 2] = e0; acc[i][j][h * 2 + 1] = e1;
                    s += e0 + e1;
                }
                s += __shfl_xor_sync(0xffffffffu, s, 1);
                s += __shfl_xor_sync(0xffffffffu, s, 2);
                sl[i][h] = s;
            }
        if (tg == 0) {
#pragma unroll
            for (int i = 0; i < 4; i++)
#pragma unroll
                for (int h = 0; h < 2; h++) {
                    int row = wm * 64 + i * 16 + h * 8 + g;
                    red[(row * 2 + seg) * 2 + pr] = sl[i][h];
                }
        }
        __syncthreads();
#pragma unroll
        for (int i = 0; i < 4; i++)
#pragma unroll
            for (int h = 0; h < 2; h++) {
                int row = wm * 64 + i * 16 + h * 8 + g;
                float inv = 1.0f / (red[(row * 2 + seg) * 2 + 0] +
                                    red[(row * 2 + seg) * 2 + 1]);
#pragma unroll
                for (int j = 0; j < 4; j++) {
                    acc[i][j][h * 2]     *= inv;
                    acc[i][j][h * 2 + 1] *= inv;
                }
            }
    }

#pragma unroll
    for (int i = 0; i < 4; i++) {
        const int r0 = m0 + wm * 64 + i * 16 + g;
#pragma unroll
        for (int j = 0; j < 4; j++) {
            const int cc = n0 + wn * 32 + j * 8 + tg * 2;
            *(float2*)&Out[(size_t)r0 * DIM + cc] = make_float2(acc[i][j][0], acc[i][j][1]);
            *(float2*)&Out[(size_t)(r0 + 8) * DIM + cc] = make_float2(acc[i][j][2], acc[i][j][3]);
        }
    }
}

// ---------------- per-chunk KV outer-product sums ----------------
__global__ __launch_bounds__(256)
void chunk_kv()
{
    extern __shared__ float sm[];
    float* ks = sm;          // 128*64
    float* vs = sm + 8192;   // 128*64

    const int c = blockIdx.x;
    const int nh = blockIdx.y;
    const int n = nh >> 4, h = nh & 15;
    const int t0 = c * CHK;
    const size_t base = ((size_t)(n * LSEQ + t0)) * DIM + h * DH;

    for (int idx = threadIdx.x; idx < CHK * DH; idx += 256) {
        int row = idx >> 6, col = idx & 63;
        ks[idx] = g_K[base + (size_t)row * DIM + col];
        vs[idx] = g_V[base + (size_t)row * DIM + col];
    }
    __syncthreads();

    const int tx = threadIdx.x & 15;
    const int ty = threadIdx.x >> 4;
    float acc[4][4];
#pragma unroll
    for (int i = 0; i < 4; i++)
#pragma unroll
        for (int j = 0; j < 4; j++) acc[i][j] = 0.f;

    for (int t = 0; t < CHK; t += 2) {
        float4 a0 = *(const float4*)&ks[t * 64 + ty * 4];
        float4 b0 = *(const float4*)&vs[t * 64 + tx * 4];
        float4 a1 = *(const float4*)&ks[(t + 1) * 64 + ty * 4];
        float4 b1 = *(const float4*)&vs[(t + 1) * 64 + tx * 4];
        const float a0v[4] = {a0.x, a0.y, a0.z, a0.w};
        const float b0v[4] = {b0.x, b0.y, b0.z, b0.w};
        const float a1v[4] = {a1.x, a1.y, a1.z, a1.w};
        const float b1v[4] = {b1.x, b1.y, b1.z, b1.w};
#pragma unroll
        for (int i = 0; i < 4; i++)
#pragma unroll
            for (int j = 0; j < 4; j++)
                acc[i][j] = fmaf(a0v[i], b0v[j], acc[i][j]);
#pragma unroll
        for (int i = 0; i < 4; i++)
#pragma unroll
            for (int j = 0; j < 4; j++)
                acc[i][j] = fmaf(a1v[i], b1v[j], acc[i][j]);
    }

    float* P = g_P + ((size_t)nh * NCHK + c) * (DH * DH);
#pragma unroll
    for (int i = 0; i < 4; i++)
#pragma unroll
        for (int j = 0; j < 4; j++)
            P[(ty * 4 + i) * 64 + tx * 4 + j] = acc[i][j];
}

// ---------------- exclusive prefix over chunks ----------------
__global__ __launch_bounds__(512)
void prefix_kv()
{
    const int nh = blockIdx.x >> 3;
    const int slab = blockIdx.x & 7;
    float* P = g_P + (size_t)nh * NCHK * (DH * DH);
    const int idx = slab * 512 + threadIdx.x;
    float run = 0.f;
#pragma unroll
    for (int c = 0; c < NCHK; c++) {
        float t = P[c * (DH * DH) + idx];
        P[c * (DH * DH) + idx] = run;
        run += t;
    }
}

// ---------------- attention output (112.5 KB smem -> 2 CTA/SM) ----------------
// Sequenced stages with one 16KB aux buffer:
//   1. load qs + kT half0 -> Am[:,0:64]        (all rows)
//   2. load kT half1      -> Am[64:128,64:128] (+ zero Am[0:64,64:128])
//   3. load Ss            -> o  = q @ S_excl
//   4. load vs over qs    -> o += triangular(A) @ v
#define QSP 65
#define AO_QS    0
#define AO_AM    (128 * QSP)               // 8320 floats
#define AO_AUX   (AO_AM + 128 * 128)       // 24704 floats
#define AO_FLTS  (AO_AUX + 4096)           // 28800 floats
#define AO_BYTES (AO_FLTS * 4)             // 115200 bytes

__global__ __launch_bounds__(256, 2)
void attn_out(float* __restrict__ out)
{
    extern __shared__ float sm[];
    float* qs  = sm + AO_QS;    // 128 x 65
    float* Am  = sm + AO_AM;    // 128 x 128
    float* aux = sm + AO_AUX;   // 64 x 64 (kT half / Ss)

    const int c = blockIdx.x;
    const int nh = blockIdx.y;
    const int n = nh >> 4, h = nh & 15;
    const int t0 = c * CHK;
    const size_t base = ((size_t)(n * LSEQ + t0)) * DIM + h * DH;
    const int tid = threadIdx.x;
    const int lane = tid & 31;
    const int wid = tid >> 5;
    const int tx = tid & 15;
    const int ty = tid >> 4;

    // load qs (padded) + kT half0: aux[d][s] = K[s][d], s in [0,64)
    for (int idx = tid; idx < CHK * DH; idx += 256) {
        int row = idx >> 6, col = idx & 63;
        qs[row * QSP + col] = g_Q[base + (size_t)row * DIM + col];
    }
    for (int idx = tid; idx < 64 * 64; idx += 256) {
        int s = idx >> 6, d = idx & 63;
        aux[d * 64 + s] = g_K[base + (size_t)s * DIM + d];
    }
    __syncthreads();

    // stage 1a: Am[:, 0:64] = causal(q @ kT0); warp w -> rows [16w, 16w+16)
    {
        const int rr0 = wid * 16 + (lane >> 3) * 4;   // 4 rows/thread
        const int ss0 = (lane & 7) * 8;               // 8 cols/thread
        float acc[4][8];
#pragma unroll
        for (int i = 0; i < 4; i++)
#pragma unroll
            for (int j = 0; j < 8; j++) acc[i][j] = 0.f;
        for (int d = 0; d < DH; d++) {
            float a[4], b[8];
#pragma unroll
            for (int i = 0; i < 4; i++) a[i] = qs[(rr0 + i) * QSP + d];
#pragma unroll
            for (int j = 0; j < 8; j++) b[j] = aux[d * 64 + ss0 + j];
#pragma unroll
            for (int i = 0; i < 4; i++)
#pragma unroll
                for (int j = 0; j < 8; j++)
                    acc[i][j] = fmaf(a[i], b[j], acc[i][j]);
        }
#pragma unroll
        for (int i = 0; i < 4; i++) {
            int r = rr0 + i;
#pragma unroll
            for (int j = 0; j < 8; j++) {
                int s = ss0 + j;
                Am[r * CHK + s] = (s <= r) ? acc[i][j] : 0.f;
            }
        }
    }
    __syncthreads();

    // load kT half1: aux[d][s-64] = K[s][d], s in [64,128)
    for (int idx = tid; idx < 64 * 64; idx += 256) {
        int s = idx >> 6, d = idx & 63;
        aux[d * 64 + s] = g_K[base + (size_t)(64 + s) * DIM + d];
    }
    __syncthreads();

    // stage 1b: Am[64:128, 64:128] = causal(q @ kT1); zero Am[0:64, 64:128]
    {
        const int rr0 = 64 + wid * 8 + (lane >> 3) * 2;  // 2 rows/thread
        const int ss0 = 64 + (lane & 7) * 8;
        float acc[2][8];
#pragma unroll
        for (int i = 0; i < 2; i++)
#pragma unroll
            for (int j = 0; j < 8; j++) acc[i][j] = 0.f;
        for (int d = 0; d < DH; d++) {
            float a[2], b[8];
#pragma unroll
            for (int i = 0; i < 2; i++) a[i] = qs[(rr0 + i) * QSP + d];
#pragma unroll
            for (int j = 0; j < 8; j++) b[j] = aux[d * 64 + (ss0 - 64) + j];
#pragma unroll
            for (int i = 0; i < 2; i++)
#pragma unroll
                for (int j = 0; j < 8; j++)
                    acc[i][j] = fmaf(a[i], b[j], acc[i][j]);
        }
#pragma unroll
        for (int i = 0; i < 2; i++) {
            int r = rr0 + i;
#pragma unroll
            for (int j = 0; j < 8; j++) {
                int s = ss0 + j;
                Am[r * CHK + s] = (s <= r) ? acc[i][j] : 0.f;
            }
        }
        for (int idx = tid; idx < 64 * 64; idx += 256) {
            int r = idx >> 6, s2 = idx & 63;
            Am[r * CHK + 64 + s2] = 0.f;
        }
    }
    __syncthreads();

    // load Ss
    {
        const float* Pp = g_P + ((size_t)nh * NCHK + c) * (DH * DH);
        for (int idx = tid; idx < DH * DH; idx += 256) aux[idx] = Pp[idx];
    }
    __syncthreads();

    // o = q @ S_excl
    float o[8][4];
#pragma unroll
    for (int i = 0; i < 8; i++)
#pragma unroll
        for (int j = 0; j < 4; j++) o[i][j] = 0.f;

    for (int d = 0; d < DH; d++) {
        float a[8], b[4];
#pragma unroll
        for (int i = 0; i < 8; i++) a[i] = qs[(ty * 8 + i) * QSP + d];
#pragma unroll
        for (int j = 0; j < 4; j++) b[j] = aux[d * 64 + tx * 4 + j];
#pragma unroll
        for (int i = 0; i < 8; i++)
#pragma unroll
            for (int j = 0; j < 4; j++)
                o[i][j] = fmaf(a[i], b[j], o[i][j]);
    }
    __syncthreads();   // all warps done with qs

    // load vs (dense 128x64) over the dead qs region
    float* vs = sm + AO_QS;
    for (int idx = tid; idx < CHK * DH; idx += 256) {
        int row = idx >> 6, col = idx & 63;
        vs[idx] = g_V[base + (size_t)row * DIM + col];
    }
    __syncthreads();

    // o += triangular(A) @ v; warp rows reach 16*wid+15 -> bound s
    const int sHi = (wid + 1) * 16;
    for (int s = 0; s < sHi; s++) {
        float a[8], b[4];
#pragma unroll
        for (int i = 0; i < 8; i++) a[i] = Am[(ty * 8 + i) * CHK + s];
#pragma unroll
        for (int j = 0; j < 4; j++) b[j] = vs[s * 64 + tx * 4 + j];
#pragma unroll
        for (int i = 0; i < 8; i++)
#pragma unroll
            for (int j = 0; j < 4; j++)
                o[i][j] = fmaf(a[i], b[j], o[i][j]);
    }

#pragma unroll
    for (int i = 0; i < 8; i++) {
        int r = ty * 8 + i;
#pragma unroll
        for (int j = 0; j < 4; j++)
            out[base + (size_t)r * DIM + tx * 4 + j] = o[i][j];
    }
}

// ---------------------------------------------------------------------------
extern "C" void kernel_launch(void* const* d_in, const int* in_sizes, int n_in,
                              void* d_out, int out_size)
{
    const float* query = (const float*)d_in[0];
    const float* key   = (const float*)d_in[1];
    const float* Wq    = (const float*)d_in[2];
    const float* Wk    = (const float*)d_in[3];
    const float* Wv    = (const float*)d_in[4];
    float* out = (float*)d_out;

    cudaFuncSetAttribute(proj_hmma, cudaFuncAttributeMaxDynamicSharedMemorySize, SMEM_TOTAL);
    cudaFuncSetAttribute(chunk_kv, cudaFuncAttributeMaxDynamicSharedMemorySize, 65536);
    cudaFuncSetAttribute(attn_out, cudaFuncAttributeMaxDynamicSharedMemorySize, AO_BYTES);

    // 1. split fp32 -> bf16 hi/lo
    conv_split<<<dim3(256, 5), 256>>>(query, key, Wq, Wk, Wv);

    // 2. projections on HMMA (z: 0=Q,1=K,2=V) with fused per-head softmax
    proj_hmma<<<dim3(8, 32, 3), 256, SMEM_TOTAL>>>();

    // 3. chunked causal linear attention
    dim3 agrid(NCHK, NBATCH * NH);
    chunk_kv<<<agrid, 256, 65536>>>();
    prefix_kv<<<NBATCH * NH * 8, 512>>>();
    attn_out<<<agrid, 256, AO_BYTES>>>(out);
}